// round 15
// baseline (speedup 1.0000x reference)
#include <cuda_runtime.h>
#include <math.h>

#define N_TOK 65536
#define DIM 64
#define KCODE 512
#define IN_DIM 256
#define NTILE 512                 // 128 tokens/rows per tile

// ---------------- device scratch (16B-aligned) ----------------
__device__ __align__(16) float g_zT[DIM * N_TOK];        // 2*z transposed [d][n]
__device__ __align__(16) float g_A[N_TOK];               // bit-exact ||z||^2
__device__ __align__(16) float g_B[KCODE];               // bit-exact ||e||^2
__device__ __align__(16) float g_eT[DIM * KCODE];        // codebook transposed
__device__ __align__(16) float g_table[KCODE * IN_DIM];  // cb @ dec_w
__device__ __align__(16) unsigned int g_counts[KCODE];
__device__ __align__(16) float g_loss_part[NTILE];
__device__ unsigned int g_work_enc;    // reset by vq final block (next launch)
__device__ unsigned int g_work_vq;     // reset by enc tile-65 handler
__device__ unsigned int g_tiles_done;  // monotonic; mod-512 trigger

// ---------------- encoder: persistent, bit-exact R13 core per tile --------
#define XCH 64
#define XPC 68
__global__ void __launch_bounds__(256, 2)
k_enc(const float* __restrict__ x, const float* __restrict__ w,
      const float* __restrict__ cb, const float* __restrict__ dw) {
    extern __shared__ float s[];
    float* ws = s;                   // [256][64] = 64KB (persists across tiles)
    float* xs = s + IN_DIM * DIM;    // [128][XPC]
    __shared__ int s_tile;
    int tid = threadIdx.x;

    {   // w: linear float4 copy, once per block
        const float4* wg = (const float4*)w;
        float4* w4 = (float4*)ws;
        #pragma unroll 4
        for (int i = tid; i < IN_DIM * DIM / 4; i += 256) w4[i] = wg[i];
    }

    int rg = tid >> 3, cg = tid & 7;

    while (true) {
        if (tid == 0) s_tile = (int)atomicAdd(&g_work_enc, 1u);
        __syncthreads();
        int tile = s_tile;
        if (tile >= NTILE) break;
        size_t rowbase = (size_t)tile * 128;

        float acc[4][8];
        #pragma unroll
        for (int a = 0; a < 4; a++)
            #pragma unroll
            for (int b = 0; b < 8; b++) acc[a][b] = 0.f;

        const float4* xg = (const float4*)(x + rowbase * IN_DIM);

        for (int c = 0; c < 4; c++) {
            __syncthreads();
            #pragma unroll
            for (int it = 0; it < 8; it++) {
                int idx = it * 256 + tid;
                int r = idx >> 4, q = idx & 15;
                *(float4*)(xs + r * XPC + 4 * q) = xg[(size_t)r * 64 + 16 * c + q];
            }
            __syncthreads();

            const float* xr0 = xs + (4 * rg + 0) * XPC;
            const float* xr1 = xs + (4 * rg + 1) * XPC;
            const float* xr2 = xs + (4 * rg + 2) * XPC;
            const float* xr3 = xs + (4 * rg + 3) * XPC;

            #pragma unroll
            for (int i4 = 0; i4 < XCH / 4; i4++) {
                float4 xv0 = *(const float4*)(xr0 + 4 * i4);
                float4 xv1 = *(const float4*)(xr1 + 4 * i4);
                float4 xv2 = *(const float4*)(xr2 + 4 * i4);
                float4 xv3 = *(const float4*)(xr3 + 4 * i4);
                #pragma unroll
                for (int j = 0; j < 4; j++) {
                    int i = XCH * c + 4 * i4 + j;
                    float4 wa = *(const float4*)(ws + i * DIM + 4 * cg);
                    float4 wb = *(const float4*)(ws + i * DIM + 32 + 4 * cg);
                    float wv[8] = {wa.x, wa.y, wa.z, wa.w, wb.x, wb.y, wb.z, wb.w};
                    float x0 = ((const float*)&xv0)[j];
                    float x1 = ((const float*)&xv1)[j];
                    float x2 = ((const float*)&xv2)[j];
                    float x3 = ((const float*)&xv3)[j];
                    #pragma unroll
                    for (int b = 0; b < 8; b++) {
                        acc[0][b] = fmaf(x0, wv[b], acc[0][b]);
                        acc[1][b] = fmaf(x1, wv[b], acc[1][b]);
                        acc[2][b] = fmaf(x2, wv[b], acc[2][b]);
                        acc[3][b] = fmaf(x3, wv[b], acc[3][b]);
                    }
                }
            }
        }

        // store 2*z transposed (exact doubling)
        #pragma unroll
        for (int b = 0; b < 8; b++) {
            int col = (b < 4) ? (4 * cg + b) : (32 + 4 * cg + (b - 4));
            float4 v;
            v.x = 2.0f * acc[0][b]; v.y = 2.0f * acc[1][b];
            v.z = 2.0f * acc[2][b]; v.w = 2.0f * acc[3][b];
            *(float4*)(g_zT + (size_t)col * N_TOK + rowbase + 4 * rg) = v;
        }

        // A[n]: bit-exact sequential chain (zs staged in xs region, pitch 65)
        __syncthreads();
        float* zs = xs;               // 128*65 = 8320 <= 128*68
        #pragma unroll
        for (int a = 0; a < 4; a++)
            #pragma unroll
            for (int b = 0; b < 8; b++) {
                int col = (b < 4) ? (4 * cg + b) : (32 + 4 * cg + (b - 4));
                zs[(4 * rg + a) * 65 + col] = acc[a][b];
            }
        __syncthreads();
        if (tid < 128) {
            const float* zr = zs + tid * 65;
            float sA = 0.f;
            for (int d = 0; d < DIM; d++)
                sA = __fadd_rn(sA, __fmul_rn(zr[d], zr[d]));
            g_A[rowbase + tid] = sA;
        }

        // ---- fused setup for this tile index ----
        __syncthreads();
        float* esh = xs;              // reuse xs (NOT ws: w persists)
        if (tid < DIM) esh[tid] = cb[(size_t)tile * DIM + tid];
        __syncthreads();
        {   // table row `tile`
            float accT = 0.f;
            #pragma unroll 8
            for (int d = 0; d < DIM; d++)
                accT = fmaf(esh[d], dw[d * IN_DIM + tid], accT);
            g_table[(size_t)tile * IN_DIM + tid] = accT;
        }
        if (tile < 64) {              // transpose: eT[tile][t] = cb[t][tile]
            g_eT[tile * KCODE + tid]       = cb[(size_t)tid * DIM + tile];
            g_eT[tile * KCODE + 256 + tid] = cb[(size_t)(256 + tid) * DIM + tile];
        } else if (tile == 64) {      // counts + bit-exact norms
            int k0 = tid, k1 = tid + 256;
            g_counts[k0] = 0u; g_counts[k1] = 0u;
            const float* e0 = cb + (size_t)k0 * DIM;
            const float* e1 = cb + (size_t)k1 * DIM;
            float s0 = 0.f, s1 = 0.f;
            for (int d = 0; d < DIM; d++) {
                s0 = __fadd_rn(s0, __fmul_rn(e0[d], e0[d]));
                s1 = __fadd_rn(s1, __fmul_rn(e1[d], e1[d]));
            }
            g_B[k0] = s0; g_B[k1] = s1;
        } else if (tile == 65 && tid == 0) {
            g_work_vq = 0u;           // reset vq work counter for this launch
        }
    }
}

// ---------------- VQ: persistent (grid 148), R13 core per tile ------------
// eT + Bs loaded once per block; per tile: zs/As load, argmin, gather.
// 512th completed tile's block performs the final loss/perplexity reduction.
__global__ void __launch_bounds__(512, 1) k_vq(float* __restrict__ out,
                                               int out_size) {
    extern __shared__ float s[];
    float* eT = s;                       // [64][512] = 131KB (persists)
    float* zs = s + DIM * KCODE;         // [64][128] = 32KB  (holds 2*z)
    float* Bs = zs + DIM * 128;          // [512]
    float* As = Bs + KCODE;              // [128]
    float* lred = As + 128;              // [32]
    int* sidx2 = (int*)(lred + 32);      // [128]
    __shared__ int s_tile;
    __shared__ int s_last;
    int tid = threadIdx.x;

    {   // eT + Bs: once per block
        const float4* eg = (const float4*)g_eT;
        float4* e4 = (float4*)eT;
        #pragma unroll 4
        for (int i = tid; i < DIM * KCODE / 4; i += 512) e4[i] = eg[i];
        if (tid < KCODE) Bs[tid] = g_B[tid];
    }

    int tg = tid >> 4, cg = tid & 15;
    int w = tid >> 5, lane = tid & 31;
    bool doFinal = false;

    while (true) {
        if (tid == 0) s_tile = (int)atomicAdd(&g_work_vq, 1u);
        __syncthreads();
        int tile = s_tile;
        if (tile >= NTILE) break;
        size_t base = (size_t)tile * 128;

        #pragma unroll
        for (int it = 0; it < 4; it++) {
            int idx = it * 512 + tid;
            int d = idx >> 5, q = idx & 31;
            *(float4*)(zs + d * 128 + 4 * q) =
                *(const float4*)(g_zT + (size_t)d * N_TOK + base + 4 * q);
        }
        if (tid < 128) As[tid] = g_A[base + tid];
        __syncthreads();

        float best[4];
        int bidx[4];
        #pragma unroll
        for (int t = 0; t < 4; t++) { best[t] = 3.4e38f; bidx[t] = 0; }
        float a0 = As[4 * tg + 0], a1 = As[4 * tg + 1];
        float a2 = As[4 * tg + 2], a3 = As[4 * tg + 3];

        #pragma unroll
        for (int pass = 0; pass < 4; pass++) {
            float m[4][8];
            #pragma unroll
            for (int t = 0; t < 4; t++)
                #pragma unroll
                for (int c = 0; c < 8; c++) m[t][c] = 0.f;

            const float* e1 = eT + pass * 128 + 4 * cg;
            const float* e2 = eT + pass * 128 + 64 + 4 * cg;
            #pragma unroll 4
            for (int d = 0; d < DIM; d++) {
                float4 zf = *(const float4*)(zs + d * 128 + 4 * tg);   // 2*z
                float4 ea = *(const float4*)(e1 + d * KCODE);
                float4 eb = *(const float4*)(e2 + d * KCODE);
                float ev[8] = {ea.x, ea.y, ea.z, ea.w, eb.x, eb.y, eb.z, eb.w};
                #pragma unroll
                for (int c = 0; c < 8; c++) {
                    m[0][c] = fmaf(zf.x, ev[c], m[0][c]);
                    m[1][c] = fmaf(zf.y, ev[c], m[1][c]);
                    m[2][c] = fmaf(zf.z, ev[c], m[2][c]);
                    m[3][c] = fmaf(zf.w, ev[c], m[3][c]);
                }
            }
            float av[4] = {a0, a1, a2, a3};
            #pragma unroll
            for (int c = 0; c < 8; c++) {
                int k = pass * 128 + ((c < 4) ? (4 * cg + c) : (64 + 4 * cg + (c - 4)));
                float bk = Bs[k];
                #pragma unroll
                for (int t = 0; t < 4; t++) {
                    float dd = __fsub_rn(__fadd_rn(av[t], bk), m[t][c]);
                    // within-thread k ascending -> strict < = first occurrence
                    if (dd < best[t]) { best[t] = dd; bidx[t] = k; }
                }
            }
        }

        // lexicographic (dist, index) min across the 16 cg lanes
        #pragma unroll
        for (int off = 8; off >= 1; off >>= 1) {
            #pragma unroll
            for (int t = 0; t < 4; t++) {
                float od = __shfl_xor_sync(0xffffffffu, best[t], off);
                int oi = __shfl_xor_sync(0xffffffffu, bidx[t], off);
                if (od < best[t] || (od == best[t] && oi < bidx[t])) {
                    best[t] = od; bidx[t] = oi;
                }
            }
        }

        if (cg == 0) {
            float ls = 0.f;
            #pragma unroll
            for (int t = 0; t < 4; t++) {
                sidx2[4 * tg + t] = bidx[t];
                atomicAdd(&g_counts[bidx[t]], 1u);
                ls += best[t];          // dist == ||z - e||^2 (loose tolerance)
            }
            lred[tg] = ls;
        }
        __syncthreads();
        if (tid == 0) {
            float acc = 0.f;
            #pragma unroll
            for (int t = 0; t < 32; t++) acc += lred[t];
            g_loss_part[tile] = acc;
        }

        // ---- fused gather: out[n][i] = table[idx[n]][i] ----
        float* og = out + 1;
        const float4* tbl4 = (const float4*)g_table;
        #pragma unroll
        for (int t = 0; t < 8; t++) {
            int tok = 8 * w + t;
            const float4* src = tbl4 + (size_t)sidx2[tok] * (IN_DIM / 4);
            float* o = og + (base + tok) * IN_DIM;
            #pragma unroll
            for (int h = 0; h < 2; h++) {
                int c4 = 32 * h + lane;
                float4 v = src[c4];
                float* p = o + 4 * c4;
                p[0] = v.x; p[1] = v.y; p[2] = v.z; p[3] = v.w;
            }
        }

        // ---- tile completion; mod-512 trigger selects the final block ----
        __syncthreads();
        if (tid == 0) {
            __threadfence();
            unsigned old = atomicAdd(&g_tiles_done, 1u);
            s_last = (((old + 1u) & (NTILE - 1u)) == 0u);
        }
        __syncthreads();
        if (s_last) doFinal = true;
    }

    if (doFinal) {
        __threadfence();                  // acquire other blocks' writes
        float* red = s;                   // eT region no longer needed
        unsigned int cnt = g_counts[tid];
        float p = (float)cnt * (1.0f / (float)N_TOK);
        red[tid] = p * logf(p + 1e-10f);
        __syncthreads();
        for (int st = 256; st > 0; st >>= 1) {
            if (tid < st) red[tid] += red[tid + st];
            __syncthreads();
        }
        float ent = -red[0];
        __syncthreads();

        red[tid] = g_loss_part[tid];
        __syncthreads();
        for (int st = 256; st > 0; st >>= 1) {
            if (tid < st) red[tid] += red[tid + st];
            __syncthreads();
        }
        if (tid == 0) {
            out[0] = 1.25f * red[0] / (float)((size_t)N_TOK * DIM);
            out[out_size - 1] = expf(ent);
            g_work_enc = 0u;              // reset for next launch (graph replay)
        }
    }
}

// ---------------- launch ----------------
extern "C" void kernel_launch(void* const* d_in, const int* in_sizes, int n_in,
                              void* d_out, int out_size) {
    const float* x = nullptr;
    const float* enc_w = nullptr;
    const float* dec_w = nullptr;
    const float* cb = nullptr;
    for (int i = 0; i < n_in; i++) {
        const float* p = (const float*)d_in[i];
        int sz = in_sizes[i];
        if (sz == N_TOK * IN_DIM) x = p;
        else if (sz == KCODE * DIM) cb = p;
        else if (sz == IN_DIM * DIM) { if (!enc_w) enc_w = p; else dec_w = p; }
    }

    const int SM_ENC = (IN_DIM * DIM + 128 * XPC) * 4;                         // 100352
    const int SM_VQ  = (DIM * KCODE + DIM * 128 + KCODE + 128 + 32 + 128) * 4; // 166976
    cudaFuncSetAttribute(k_enc, cudaFuncAttributeMaxDynamicSharedMemorySize, SM_ENC);
    cudaFuncSetAttribute(k_vq,  cudaFuncAttributeMaxDynamicSharedMemorySize, SM_VQ);

    float* out = (float*)d_out;

    k_enc<<<296, 256, SM_ENC>>>(x, enc_w, cb, dec_w);   // 2 CTA/SM persistent
    k_vq<<<148, 512, SM_VQ>>>(out, out_size);           // 1 CTA/SM persistent
}

// round 16
// speedup vs baseline: 1.0105x; 1.0105x over previous
#include <cuda_runtime.h>
#include <math.h>

#define N_TOK 65536
#define DIM 64
#define KCODE 512
#define IN_DIM 256

// ---------------- device scratch (16B-aligned) ----------------
__device__ __align__(16) float g_zT[DIM * N_TOK];        // 2*z transposed [d][n]
__device__ __align__(16) float g_A[N_TOK];               // bit-exact ||z||^2
__device__ __align__(16) float g_B[KCODE];               // bit-exact ||e||^2
__device__ __align__(16) float g_eT[DIM * KCODE];        // codebook transposed
__device__ __align__(16) float g_tbl_s[KCODE * IN_DIM];  // SHIFTED cb@dec_w rows:
    // row k: float4 j(0..62) = row[4j+3..4j+6]; float4 63 = {row0,row1,row2,row255}
__device__ __align__(16) unsigned int g_counts[KCODE];
__device__ __align__(16) float g_loss_part[512];
__device__ unsigned int g_done;                          // vq completion counter

// ---------------- encoder: z = x @ enc_w (bit-exact chains; R13 core) -----
// Fused setup: block bk writes shifted-table row bk; blocks 0..63 transpose
// eT row; 64 does counts+norms; 65 resets g_done.
#define XCH 64
#define XPC 68
__global__ void __launch_bounds__(256, 2)
k_enc(const float* __restrict__ x, const float* __restrict__ w,
      const float* __restrict__ cb, const float* __restrict__ dw) {
    extern __shared__ float s[];
    float* ws = s;                   // [256][64] = 64KB
    float* xs = s + IN_DIM * DIM;    // [128][XPC]
    int tid = threadIdx.x;
    int blk = blockIdx.x;
    size_t rowbase = (size_t)blk * 128;

    {
        const float4* wg = (const float4*)w;
        float4* w4 = (float4*)ws;
        #pragma unroll 4
        for (int i = tid; i < IN_DIM * DIM / 4; i += 256) w4[i] = wg[i];
    }

    int rg = tid >> 3, cg = tid & 7;
    float acc[4][8];
    #pragma unroll
    for (int a = 0; a < 4; a++)
        #pragma unroll
        for (int b = 0; b < 8; b++) acc[a][b] = 0.f;

    const float4* xg = (const float4*)(x + rowbase * IN_DIM);

    for (int c = 0; c < 4; c++) {
        __syncthreads();
        #pragma unroll
        for (int it = 0; it < 8; it++) {
            int idx = it * 256 + tid;
            int r = idx >> 4, q = idx & 15;
            *(float4*)(xs + r * XPC + 4 * q) = xg[(size_t)r * 64 + 16 * c + q];
        }
        __syncthreads();

        const float* xr0 = xs + (4 * rg + 0) * XPC;
        const float* xr1 = xs + (4 * rg + 1) * XPC;
        const float* xr2 = xs + (4 * rg + 2) * XPC;
        const float* xr3 = xs + (4 * rg + 3) * XPC;

        #pragma unroll
        for (int i4 = 0; i4 < XCH / 4; i4++) {
            float4 xv0 = *(const float4*)(xr0 + 4 * i4);
            float4 xv1 = *(const float4*)(xr1 + 4 * i4);
            float4 xv2 = *(const float4*)(xr2 + 4 * i4);
            float4 xv3 = *(const float4*)(xr3 + 4 * i4);
            #pragma unroll
            for (int j = 0; j < 4; j++) {
                int i = XCH * c + 4 * i4 + j;
                float4 wa = *(const float4*)(ws + i * DIM + 4 * cg);
                float4 wb = *(const float4*)(ws + i * DIM + 32 + 4 * cg);
                float wv[8] = {wa.x, wa.y, wa.z, wa.w, wb.x, wb.y, wb.z, wb.w};
                float x0 = ((const float*)&xv0)[j];
                float x1 = ((const float*)&xv1)[j];
                float x2 = ((const float*)&xv2)[j];
                float x3 = ((const float*)&xv3)[j];
                #pragma unroll
                for (int b = 0; b < 8; b++) {
                    acc[0][b] = fmaf(x0, wv[b], acc[0][b]);
                    acc[1][b] = fmaf(x1, wv[b], acc[1][b]);
                    acc[2][b] = fmaf(x2, wv[b], acc[2][b]);
                    acc[3][b] = fmaf(x3, wv[b], acc[3][b]);
                }
            }
        }
    }

    #pragma unroll
    for (int b = 0; b < 8; b++) {
        int col = (b < 4) ? (4 * cg + b) : (32 + 4 * cg + (b - 4));
        float4 v;
        v.x = 2.0f * acc[0][b]; v.y = 2.0f * acc[1][b];
        v.z = 2.0f * acc[2][b]; v.w = 2.0f * acc[3][b];
        *(float4*)(g_zT + (size_t)col * N_TOK + rowbase + 4 * rg) = v;
    }

    __syncthreads();
    float* zs = xs;
    #pragma unroll
    for (int a = 0; a < 4; a++)
        #pragma unroll
        for (int b = 0; b < 8; b++) {
            int col = (b < 4) ? (4 * cg + b) : (32 + 4 * cg + (b - 4));
            zs[(4 * rg + a) * 65 + col] = acc[a][b];
        }
    __syncthreads();
    if (tid < 128) {
        const float* zr = zs + tid * 65;
        float sA = 0.f;
        for (int d = 0; d < DIM; d++)
            sA = __fadd_rn(sA, __fmul_rn(zr[d], zr[d]));
        g_A[rowbase + tid] = sA;
    }

    // ---- fused setup: shifted table row blk + transpose/norms ----
    __syncthreads();
    float* esh = s;                       // [64] cb row
    float* sT = s + 64;                   // [256] table-row staging
    if (tid < DIM) esh[tid] = cb[(size_t)blk * DIM + tid];
    __syncthreads();
    {
        float accT = 0.f;
        #pragma unroll 8
        for (int d = 0; d < DIM; d++)
            accT = fmaf(esh[d], dw[d * IN_DIM + tid], accT);
        sT[tid] = accT;
    }
    __syncthreads();
    if (tid < 63) {                       // shifted quads
        float4 v;
        v.x = sT[4 * tid + 3]; v.y = sT[4 * tid + 4];
        v.z = sT[4 * tid + 5]; v.w = sT[4 * tid + 6];
        *(float4*)(g_tbl_s + (size_t)blk * IN_DIM + 4 * tid) = v;
    } else if (tid == 63) {               // edge quad
        float4 v;
        v.x = sT[0]; v.y = sT[1]; v.z = sT[2]; v.w = sT[255];
        *(float4*)(g_tbl_s + (size_t)blk * IN_DIM + 252) = v;
    }

    if (blk < 64) {                       // transpose: eT[blk][t]
        g_eT[blk * KCODE + tid]       = cb[(size_t)tid * DIM + blk];
        g_eT[blk * KCODE + 256 + tid] = cb[(size_t)(256 + tid) * DIM + blk];
    } else if (blk == 64) {               // counts + bit-exact norms
        int k0 = tid, k1 = tid + 256;
        g_counts[k0] = 0u; g_counts[k1] = 0u;
        const float* e0 = cb + (size_t)k0 * DIM;
        const float* e1 = cb + (size_t)k1 * DIM;
        float s0 = 0.f, s1 = 0.f;
        for (int d = 0; d < DIM; d++) {
            s0 = __fadd_rn(s0, __fmul_rn(e0[d], e0[d]));
            s1 = __fadd_rn(s1, __fmul_rn(e1[d], e1[d]));
        }
        g_B[k0] = s0; g_B[k1] = s1;
    } else if (blk == 65 && tid == 0) {
        g_done = 0u;
    }
}

// ---------------- VQ (R13 core) + vectorized gather + last-block final ----
__global__ void __launch_bounds__(512, 1) k_vq(float* __restrict__ out,
                                               int out_size) {
    extern __shared__ float s[];
    float* eT = s;                       // [64][512] = 131KB
    float* zs = s + DIM * KCODE;         // [64][128] = 32KB  (holds 2*z)
    float* Bs = zs + DIM * 128;          // [512]
    float* As = Bs + KCODE;              // [128]
    float* lred = As + 128;              // [32]
    int* sidx2 = (int*)(lred + 32);      // [128]
    int tid = threadIdx.x;
    size_t base = (size_t)blockIdx.x * 128;

    {
        const float4* eg = (const float4*)g_eT;
        float4* e4 = (float4*)eT;
        #pragma unroll 4
        for (int i = tid; i < DIM * KCODE / 4; i += 512) e4[i] = eg[i];
        #pragma unroll
        for (int it = 0; it < 4; it++) {
            int idx = it * 512 + tid;
            int d = idx >> 5, q = idx & 31;
            *(float4*)(zs + d * 128 + 4 * q) =
                *(const float4*)(g_zT + (size_t)d * N_TOK + base + 4 * q);
        }
        if (tid < KCODE) Bs[tid] = g_B[tid];
        if (tid < 128) As[tid] = g_A[base + tid];
    }
    __syncthreads();

    int tg = tid >> 4, cg = tid & 15;
    float best[4];
    int bidx[4];
    #pragma unroll
    for (int t = 0; t < 4; t++) { best[t] = 3.4e38f; bidx[t] = 0; }
    float a0 = As[4 * tg + 0], a1 = As[4 * tg + 1];
    float a2 = As[4 * tg + 2], a3 = As[4 * tg + 3];

    #pragma unroll
    for (int pass = 0; pass < 4; pass++) {
        float m[4][8];
        #pragma unroll
        for (int t = 0; t < 4; t++)
            #pragma unroll
            for (int c = 0; c < 8; c++) m[t][c] = 0.f;

        const float* e1 = eT + pass * 128 + 4 * cg;
        const float* e2 = eT + pass * 128 + 64 + 4 * cg;
        #pragma unroll 4
        for (int d = 0; d < DIM; d++) {
            float4 zf = *(const float4*)(zs + d * 128 + 4 * tg);   // 2*z
            float4 ea = *(const float4*)(e1 + d * KCODE);
            float4 eb = *(const float4*)(e2 + d * KCODE);
            float ev[8] = {ea.x, ea.y, ea.z, ea.w, eb.x, eb.y, eb.z, eb.w};
            #pragma unroll
            for (int c = 0; c < 8; c++) {
                m[0][c] = fmaf(zf.x, ev[c], m[0][c]);
                m[1][c] = fmaf(zf.y, ev[c], m[1][c]);
                m[2][c] = fmaf(zf.z, ev[c], m[2][c]);
                m[3][c] = fmaf(zf.w, ev[c], m[3][c]);
            }
        }
        float av[4] = {a0, a1, a2, a3};
        #pragma unroll
        for (int c = 0; c < 8; c++) {
            int k = pass * 128 + ((c < 4) ? (4 * cg + c) : (64 + 4 * cg + (c - 4)));
            float bk = Bs[k];
            #pragma unroll
            for (int t = 0; t < 4; t++) {
                float dd = __fsub_rn(__fadd_rn(av[t], bk), m[t][c]);
                // within-thread k ascending -> strict < = first occurrence
                if (dd < best[t]) { best[t] = dd; bidx[t] = k; }
            }
        }
    }

    // lexicographic (dist, index) min across the 16 cg lanes
    #pragma unroll
    for (int off = 8; off >= 1; off >>= 1) {
        #pragma unroll
        for (int t = 0; t < 4; t++) {
            float od = __shfl_xor_sync(0xffffffffu, best[t], off);
            int oi = __shfl_xor_sync(0xffffffffu, bidx[t], off);
            if (od < best[t] || (od == best[t] && oi < bidx[t])) {
                best[t] = od; bidx[t] = oi;
            }
        }
    }

    if (cg == 0) {
        float ls = 0.f;
        #pragma unroll
        for (int t = 0; t < 4; t++) {
            sidx2[4 * tg + t] = bidx[t];
            atomicAdd(&g_counts[bidx[t]], 1u);
            ls += best[t];          // dist == ||z - e||^2 (loose tolerance)
        }
        lred[tg] = ls;
    }
    __syncthreads();
    if (tid == 0) {
        float acc = 0.f;
        #pragma unroll
        for (int t = 0; t < 32; t++) acc += lred[t];
        g_loss_part[blockIdx.x] = acc;
    }

    // ---- vectorized gather from SHIFTED table ----
    // Token row at out+1+(base+tok)*256: quads [3+4j..6+4j] are 16B-aligned.
    {
        int w = tid >> 5, lane = tid & 31;
        const float4* tbl4 = (const float4*)g_tbl_s;
        #pragma unroll
        for (int t = 0; t < 8; t++) {
            int tok = 8 * w + t;
            const float4* src = tbl4 + (size_t)sidx2[tok] * 64;
            float* o = out + 1 + (base + tok) * IN_DIM;
            // chunks j = lane (0..31)
            if (lane < 32) {
                float4 v = src[lane];
                if (lane == 31) {                 // src[31] is a shifted quad too
                    *(float4*)(o + 3 + 4 * 31) = v;
                } else {
                    *(float4*)(o + 3 + 4 * lane) = v;
                }
            }
            // chunks j = 32+lane (32..62) ; lane 31 handles edges
            if (lane < 31) {
                float4 v = src[32 + lane];
                *(float4*)(o + 3 + 4 * (32 + lane)) = v;
            } else {
                float4 e = src[63];               // {row0,row1,row2,row255}
                o[0] = e.x; o[1] = e.y; o[2] = e.z; o[255] = e.w;
            }
        }
    }

    // ---- last-block final: loss + perplexity ----
    __threadfence();
    __shared__ unsigned int isLast;
    if (tid == 0) isLast = (atomicAdd(&g_done, 1u) == (unsigned)(gridDim.x - 1));
    __syncthreads();
    if (isLast) {
        float* red = s;                   // reuse smem
        unsigned int cnt = g_counts[tid];
        float p = (float)cnt * (1.0f / (float)N_TOK);
        red[tid] = p * logf(p + 1e-10f);
        __syncthreads();
        for (int st = 256; st > 0; st >>= 1) {
            if (tid < st) red[tid] += red[tid + st];
            __syncthreads();
        }
        float ent = -red[0];
        __syncthreads();

        red[tid] = g_loss_part[tid];
        __syncthreads();
        for (int st = 256; st > 0; st >>= 1) {
            if (tid < st) red[tid] += red[tid + st];
            __syncthreads();
        }
        if (tid == 0) {
            out[0] = 1.25f * red[0] / (float)((size_t)N_TOK * DIM);
            out[out_size - 1] = expf(ent);
        }
    }
}

// ---------------- launch ----------------
extern "C" void kernel_launch(void* const* d_in, const int* in_sizes, int n_in,
                              void* d_out, int out_size) {
    const float* x = nullptr;
    const float* enc_w = nullptr;
    const float* dec_w = nullptr;
    const float* cb = nullptr;
    for (int i = 0; i < n_in; i++) {
        const float* p = (const float*)d_in[i];
        int sz = in_sizes[i];
        if (sz == N_TOK * IN_DIM) x = p;
        else if (sz == KCODE * DIM) cb = p;
        else if (sz == IN_DIM * DIM) { if (!enc_w) enc_w = p; else dec_w = p; }
    }

    const int SM_ENC = (IN_DIM * DIM + 128 * XPC) * 4;                         // 100352
    const int SM_VQ  = (DIM * KCODE + DIM * 128 + KCODE + 128 + 32 + 128) * 4; // 166976
    cudaFuncSetAttribute(k_enc, cudaFuncAttributeMaxDynamicSharedMemorySize, SM_ENC);
    cudaFuncSetAttribute(k_vq,  cudaFuncAttributeMaxDynamicSharedMemorySize, SM_VQ);

    float* out = (float*)d_out;

    k_enc<<<N_TOK / 128, 256, SM_ENC>>>(x, enc_w, cb, dec_w);
    k_vq<<<N_TOK / 128, 512, SM_VQ>>>(out, out_size);
}